// round 11
// baseline (speedup 1.0000x reference)
#include <cuda_runtime.h>
#include <cstdint>

#define BB 64
#define TT 512
#define HH 768
#define KK 11
#define START_ID 9
#define END_ID 10
#define NEGV (-10000.0f)

#define NSCAN 32                 // dual-batch scan blocks
#define NPRODB 116               // producer blocks
#define GRID (NSCAN + NPRODB)    // 148 = one full wave, co-resident
#define THREADS 512

__device__ __align__(16) float g_feats[TT * BB * KK];   // [t][b][k] t-major
__device__ int g_tflag[TT];

// ---- dynamic smem layout (scan blocks) ----
#define SFEAT_BYTES  ((TT + 8) * 12 * 4)   // 24960
#define SDELTA_BYTES (TT * 12 * 4)         // 24576
#define PSEG_BYTES   (16 * KK * 32)        // 5632
#define OFF_SFEAT0   0
#define OFF_SFEAT1   (OFF_SFEAT0 + SFEAT_BYTES)
#define OFF_SDELTA0  (OFF_SFEAT1 + SFEAT_BYTES)
#define OFF_SDELTA1  (OFF_SDELTA0 + SDELTA_BYTES)
#define OFF_STRANS   (OFF_SDELTA1 + SDELTA_BYTES)
#define OFF_PSEG0    (OFF_STRANS + 512)
#define OFF_PSEG1    (OFF_PSEG0 + PSEG_BYTES)
#define OFF_ESEL0    (OFF_PSEG1 + PSEG_BYTES)
#define OFF_ESEL1    (OFF_ESEL0 + 16)
#define OFF_PROG     (OFF_ESEL1 + 16)      // 14 ints
#define OFF_LT       (OFF_PROG + 64)       // 2 ints
#define SMEM_SCAN    (OFF_LT + 16)         // ~111 KB
#define SMEM_PROD    (HH * KK * 4)         // 33792
#define SMEM_TOTAL   (SMEM_SCAN > SMEM_PROD ? SMEM_SCAN : SMEM_PROD)

extern __shared__ char dsm[];

__global__ void zero_flags_kernel() {
    if (threadIdx.x < TT) g_tflag[threadIdx.x] = 0;
}

// ---------------------------------------------------------------------------
// psi recompute: argmax_j (trans[tag][j] + delta[t-1][j]), first-max wins.
// Only j=0..8 can win for t>=2; at t=1 winner is START. Bit-exact.
// ---------------------------------------------------------------------------
__device__ __forceinline__ int psi_step(const float* __restrict__ strans,
                                        const float* __restrict__ sdelta,
                                        int t, int tag)
{
    if (t == 1) return START_ID;
    const float* tr = strans + tag * KK;
    const float* d = sdelta + (t - 1) * 12;
    float s[9];
#pragma unroll
    for (int j = 0; j < 9; j++) s[j] = tr[j] + d[j];
    float m = s[0];
#pragma unroll
    for (int j = 1; j < 9; j++) m = fmaxf(m, s[j]);
    unsigned msk = 0;
#pragma unroll
    for (int j = 0; j < 9; j++) msk |= (s[j] == m) ? (1u << j) : 0u;
    return __ffs(msk) - 1;
}

// ---------------------------------------------------------------------------
// Scan warp: proven R8 loop (sfeat stride 12), gated by stager progress.
// ---------------------------------------------------------------------------
__device__ __forceinline__ void scan_warp(
    float* sfeat, float* sdelta, const float* strans,
    volatile int* pv, int lane, int b, float* out, int* lt)
{
    const int target = (lane <= 8) ? lane : END_ID;
    const int slot4 = ((lane <= 8) ? lane : 9) * 4;

    float tr0 = strans[target * KK + 0], tr1 = strans[target * KK + 1];
    float tr2 = strans[target * KK + 2], tr3 = strans[target * KK + 3];
    float tr4 = strans[target * KK + 4], tr5 = strans[target * KK + 5];
    float tr6 = strans[target * KK + 6], tr7 = strans[target * KK + 7];
    float tr8 = strans[target * KK + 8], tr9 = strans[target * KK + 9];

    const unsigned sd_base = (unsigned)__cvta_generic_to_shared(sdelta);

#define WAITM(X)                                                               \
    {                                                                          \
        int m_;                                                                \
        do {                                                                   \
            m_ = pv[0]; m_ = min(m_, pv[1]); m_ = min(m_, pv[2]);              \
            m_ = min(m_, pv[3]); m_ = min(m_, pv[4]); m_ = min(m_, pv[5]);     \
            m_ = min(m_, pv[6]);                                               \
        } while (m_ < (X));                                                    \
        asm volatile("" ::: "memory");                                         \
    }

    WAITM(13);

    float d0, d1, d2, d3, d4, d5, d6, d7, d8;

    // ---- t = 1 closed form: predecessor is START (certain) ----
    {
        float nd1 = (tr9 + 0.0f) + sfeat[12 + target];
        unsigned row1 = sd_base + 48;
        asm volatile("st.shared.f32 [%0], %1;"
                     :: "r"(row1 + slot4), "f"(nd1) : "memory");
        asm volatile("ld.shared.v4.f32 {%0,%1,%2,%3}, [%4];"
                     : "=f"(d0), "=f"(d1), "=f"(d2), "=f"(d3)
                     : "r"(row1) : "memory");
        asm volatile("ld.shared.v4.f32 {%0,%1,%2,%3}, [%4+16];"
                     : "=f"(d4), "=f"(d5), "=f"(d6), "=f"(d7)
                     : "r"(row1) : "memory");
        asm volatile("ld.shared.f32 %0, [%1+32];"
                     : "=f"(d8) : "r"(row1) : "memory");
    }

    float fbuf[6];
#pragma unroll
    for (int s = 0; s < 6; s++) fbuf[s] = sfeat[(2 + s) * 12 + target];
    const float* fpre = sfeat + 8 * 12 + target;

    unsigned addr = sd_base + 96;              // row 2
    unsigned sd_store = addr + slot4;

#define VSTEP(U_, O0, O1)                                                      \
    {                                                                          \
        float f = fbuf[U_];                                                    \
        fbuf[U_] = *fpre; fpre += 12;                                          \
        float s0 = tr0 + d0, s1 = tr1 + d1, s2 = tr2 + d2, s3 = tr3 + d3;      \
        float s4 = tr4 + d4, s5 = tr5 + d5, s6 = tr6 + d6, s7 = tr7 + d7;      \
        float s8v = tr8 + d8;                                                  \
        float m01 = fmaxf(s0, s1), m23 = fmaxf(s2, s3);                        \
        float m45 = fmaxf(s4, s5), m67 = fmaxf(s6, s7);                        \
        float m = fmaxf(fmaxf(fmaxf(m01, m23), fmaxf(m45, m67)), s8v);         \
        float nd = m + f;                                                      \
        asm volatile("st.shared.f32 [%0+" #O0 "], %1;"                         \
                     :: "r"(sd_store), "f"(nd) : "memory");                    \
        asm volatile("ld.shared.v4.f32 {%0,%1,%2,%3}, [%4+" #O0 "];"           \
                     : "=f"(d0), "=f"(d1), "=f"(d2), "=f"(d3)                  \
                     : "r"(addr) : "memory");                                  \
        asm volatile("ld.shared.v4.f32 {%0,%1,%2,%3}, [%4+" #O1 "];"           \
                     : "=f"(d4), "=f"(d5), "=f"(d6), "=f"(d7)                  \
                     : "r"(addr) : "memory");                                  \
        asm volatile("ld.shared.f32 %0, [%1+" #O1 "+16];"                      \
                     : "=f"(d8) : "r"(addr) : "memory");                       \
    }

    int t = 2;
    for (int it = 0; it < 85; ++it) {          // 85 * 6 = 510 steps, t = 2..511
        WAITM(t + 11);
        VSTEP(0, 0, 16)
        VSTEP(1, 48, 64)
        VSTEP(2, 96, 112)
        VSTEP(3, 144, 160)
        VSTEP(4, 192, 208)
        VSTEP(5, 240, 256)
        addr += 288;
        sd_store += 288;
        t += 6;
    }
#undef VSTEP
#undef WAITM

    __syncwarp();
    float dEND = sdelta[511 * 12 + 9];

    {
        float m01 = fmaxf(d0, d1), m23 = fmaxf(d2, d3);
        float m45 = fmaxf(d4, d5), m67 = fmaxf(d6, d7);
        float m = fmaxf(fmaxf(fmaxf(m01, m23), fmaxf(m45, m67)),
                        fmaxf(d8, dEND));
        unsigned msk = (d0 == m ? 1u : 0u) | (d1 == m ? 2u : 0u) |
                       (d2 == m ? 4u : 0u) | (d3 == m ? 8u : 0u) |
                       (d4 == m ? 16u : 0u) | (d5 == m ? 32u : 0u) |
                       (d6 == m ? 64u : 0u) | (d7 == m ? 128u : 0u) |
                       (d8 == m ? 256u : 0u) |
                       (dEND == m ? (1u << END_ID) : 0u);
        if (lane == 0) {
            out[b] = m;                         // score
            *lt = __ffs(msk) - 1;
        }
    }
}

// ---------------------------------------------------------------------------
// Fused single-wave kernel.
// ---------------------------------------------------------------------------
__global__ __launch_bounds__(THREADS, 1) void fused_kernel(
    const float* __restrict__ embeds,   // [B,T,H]
    const float* __restrict__ W,        // [K,H]
    const float* __restrict__ bias,     // [K]
    const float* __restrict__ trans,    // [K,K]
    float* __restrict__ out)            // [B + B*T]
{
    const int bid = blockIdx.x;
    const int tid = threadIdx.x;
    const int wid = tid >> 5;
    const int lane = tid & 31;

    if (bid >= NSCAN) {
        // ============================ PRODUCER ============================
        float* sWt = (float*)dsm;                  // [h*11 + k], stride 11
        for (int i = tid; i < KK * HH; i += THREADS) {
            int k = i / HH, h = i - k * HH;
            sWt[h * KK + k] = W[i];
        }
        float bs[KK];
#pragma unroll
        for (int k = 0; k < KK; k++) bs[k] = __ldg(&bias[k]);
        __syncthreads();

        const int q = bid - NSCAN;
        const int brow = wid * 4;                  // this warp's 4 batches

        for (int i = 0;; ++i) {
            const int t = 1 + q + NPRODB * i;
            if (t > TT - 1) break;

            const float* Ar0 = embeds + ((size_t)(brow + 0) * TT + t) * HH;
            const float* Ar1 = embeds + ((size_t)(brow + 1) * TT + t) * HH;
            const float* Ar2 = embeds + ((size_t)(brow + 2) * TT + t) * HH;
            const float* Ar3 = embeds + ((size_t)(brow + 3) * TT + t) * HH;

            float acc[4][KK];
#pragma unroll
            for (int r = 0; r < 4; r++)
#pragma unroll
                for (int k = 0; k < KK; k++) acc[r][k] = 0.0f;

#pragma unroll
            for (int w = 0; w < 6; w++) {
                float a0[4], a1[4], a2[4], a3[4];
#pragma unroll
                for (int s = 0; s < 4; s++) {
                    int h = w * 128 + s * 32 + lane;
                    a0[s] = Ar0[h]; a1[s] = Ar1[h]; a2[s] = Ar2[h]; a3[s] = Ar3[h];
                }
#pragma unroll
                for (int s = 0; s < 4; s++) {
                    float wr[KK];
                    const float* wp = &sWt[(w * 128 + s * 32 + lane) * KK];
#pragma unroll
                    for (int k = 0; k < KK; k++) wr[k] = wp[k];
#pragma unroll
                    for (int k = 0; k < KK; k++) {
                        acc[0][k] = fmaf(a0[s], wr[k], acc[0][k]);
                        acc[1][k] = fmaf(a1[s], wr[k], acc[1][k]);
                        acc[2][k] = fmaf(a2[s], wr[k], acc[2][k]);
                        acc[3][k] = fmaf(a3[s], wr[k], acc[3][k]);
                    }
                }
            }

#pragma unroll
            for (int r = 0; r < 4; r++)
#pragma unroll
                for (int k = 0; k < KK; k++) {
                    float v = acc[r][k];
                    v += __shfl_xor_sync(0xffffffffu, v, 16);
                    v += __shfl_xor_sync(0xffffffffu, v, 8);
                    v += __shfl_xor_sync(0xffffffffu, v, 4);
                    v += __shfl_xor_sync(0xffffffffu, v, 2);
                    v += __shfl_xor_sync(0xffffffffu, v, 1);
                    acc[r][k] = v;
                }

            if (lane == 0) {
#pragma unroll
                for (int r = 0; r < 4; r++)
#pragma unroll
                    for (int k = 0; k < KK; k++)
                        g_feats[(size_t)t * (BB * KK) + (brow + r) * KK + k] =
                            acc[r][k] + bs[k];
            }
            __syncthreads();                       // all rows of t written
            if (tid == 0) {
                __threadfence();                   // publish rows, then flag
                *(volatile int*)&g_tflag[t] = 1;
            }
        }
        return;
    }

    // ============================== SCAN BLOCK ==============================
    float* sfeat0  = (float*)(dsm + OFF_SFEAT0);
    float* sfeat1  = (float*)(dsm + OFF_SFEAT1);
    float* sdelta0 = (float*)(dsm + OFF_SDELTA0);
    float* sdelta1 = (float*)(dsm + OFF_SDELTA1);
    float* strans  = (float*)(dsm + OFF_STRANS);
    unsigned char (*pseg0)[32] = (unsigned char (*)[32])(dsm + OFF_PSEG0);
    unsigned char (*pseg1)[32] = (unsigned char (*)[32])(dsm + OFF_PSEG1);
    unsigned char* esel0 = (unsigned char*)(dsm + OFF_ESEL0);
    unsigned char* esel1 = (unsigned char*)(dsm + OFF_ESEL1);
    volatile int* vprog = (volatile int*)(dsm + OFF_PROG);
    int* lt = (int*)(dsm + OFF_LT);

    const int b0 = 2 * bid, b1 = 2 * bid + 1;

    for (int i = tid; i < KK * KK; i += THREADS) strans[i] = trans[i];
    if (tid < 14) ((volatile int*)(dsm + OFF_PROG))[tid] = 73 * (tid % 7);
    __syncthreads();

    if (wid < 2) {
        // two scan warps
        scan_warp(wid ? sfeat1 : sfeat0, wid ? sdelta1 : sdelta0, strans,
                  vprog + 7 * wid, lane, wid ? b1 : b0, out, lt + wid);
    } else {
        // 14 stager warps: s = wid-2; half = s/7; j = s%7; range 73 t's
        const int s = wid - 2;
        const int half = s / 7;
        const int j = s % 7;
        const int b = half ? b1 : b0;
        float* sfeat = half ? sfeat1 : sfeat0;
        volatile int* prg = vprog + 7 * half + j;
        const int ts = 1 + 73 * j, te = 73 * (j + 1);

        for (int t0 = ts; t0 <= te; t0 += 2) {
            const int t1 = t0 + 1;
            const bool v1 = (t1 <= te);
            while (true) {
                int f = 1;
                if (lane == 0) f = *(volatile int*)&g_tflag[t0];
                else if (lane == 16 && v1) f = *(volatile int*)&g_tflag[t1];
                if (__all_sync(0xffffffffu, f != 0)) break;
            }
            __threadfence();                        // acquire before row reads
            if (lane < KK)
                sfeat[t0 * 12 + lane] =
                    g_feats[(size_t)t0 * (BB * KK) + b * KK + lane];
            else if (lane >= 16 && lane < 16 + KK && v1)
                sfeat[t1 * 12 + (lane - 16)] =
                    g_feats[(size_t)t1 * (BB * KK) + b * KK + (lane - 16)];
            __threadfence_block();
            if (lane == 0) *prg = v1 ? t1 : t0;
        }
        if (lane == 0) *prg = 9999;
    }
    __syncthreads();

    // ---- chunked backtrack (both batches), psi recomputed from deltas ----
    {
        int local = tid & 255;
        int whichb = tid >> 8;                     // 0 -> b0, 1 -> b1
        unsigned char (*pseg)[32] = whichb ? pseg1 : pseg0;
        float* sdelta = whichb ? sdelta1 : sdelta0;
        if (local < 165) {
            const int c = local / KK;
            const int e = local - c * KK;
            const int tb = 32 * c;
            int tag = e;
            for (int t = tb + 32; t > tb; --t) {
                tag = psi_step(strans, sdelta, t, tag);
                pseg[c * KK + e][t - 1 - tb] = (unsigned char)tag;
            }
        } else if (local == 165) {
            int tag = lt[whichb];
            pseg[15 * KK][31] = (unsigned char)tag;
            for (int t = TT - 1; t > 480; --t) {
                tag = psi_step(strans, sdelta, t, tag);
                pseg[15 * KK][t - 1 - 480] = (unsigned char)tag;
            }
        }
    }
    __syncthreads();

    if (tid == 0 || tid == 256) {
        int whichb = tid >> 8;
        unsigned char (*pseg)[32] = whichb ? pseg1 : pseg0;
        unsigned char* esel = whichb ? esel1 : esel0;
        esel[15] = 0;
        int btag = pseg[15 * KK][0];
        for (int c = 14; c >= 0; --c) {
            esel[c] = (unsigned char)btag;
            btag = pseg[c * KK + btag][0];
        }
    }
    __syncthreads();

    {
        int whichb = tid >> 8;
        int b = whichb ? b1 : b0;
        unsigned char (*pseg)[32] = whichb ? pseg1 : pseg0;
        unsigned char* esel = whichb ? esel1 : esel0;
        for (int p = tid & 255; p < TT; p += 256) {
            int c = p >> 5;
            out[BB + (size_t)b * TT + p] = (float)pseg[c * KK + esel[c]][p & 31];
        }
    }
}

// ---------------------------------------------------------------------------
extern "C" void kernel_launch(void* const* d_in, const int* in_sizes, int n_in,
                              void* d_out, int out_size)
{
    const float* embeds = (const float*)d_in[0];   // [B,T,H]
    const float* W_fc   = (const float*)d_in[1];   // [K,H]
    const float* b_fc   = (const float*)d_in[2];   // [K]
    const float* trans  = (const float*)d_in[3];   // [K,K]
    float* out = (float*)d_out;

    cudaFuncSetAttribute(fused_kernel,
                         cudaFuncAttributeMaxDynamicSharedMemorySize, SMEM_TOTAL);
    zero_flags_kernel<<<1, TT>>>();
    fused_kernel<<<GRID, THREADS, SMEM_TOTAL>>>(embeds, W_fc, b_fc, trans, out);
}

// round 12
// speedup vs baseline: 1.2563x; 1.2563x over previous
#include <cuda_runtime.h>
#include <cstdint>

#define BB 64
#define TT 512
#define HH 768
#define KK 11
#define START_ID 9
#define END_ID 10
#define NEGV (-10000.0f)

#define NSCAN 64
#define NPRODB 512               // 64 b x 8 chunks of 64 t
#define GRID (NSCAN + NPRODB)
#define THREADS 512
#define SMEM_LAUNCH (120*1024)   // forces 1 block/SM (isolation)

__device__ __align__(16) float g_feats[BB * TT * KK + 128];  // [b][t][k] + pad
__device__ int g_cflag[BB * 8];                              // [b][chunk]

extern __shared__ char dsm[];

__global__ void zero_flags_kernel() {
    g_cflag[threadIdx.x] = 0;     // 512 threads, exact
}

// ---------------------------------------------------------------------------
// psi recompute: argmax_j (trans[tag][j] + delta[t-1][j]), first-max wins.
// Only j=0..8 can win for t>=2; at t=1 winner is START. Bit-exact.
// ---------------------------------------------------------------------------
__device__ __forceinline__ int psi_step(const float* __restrict__ strans,
                                        const float* __restrict__ sdelta,
                                        int t, int tag)
{
    if (t == 1) return START_ID;
    const float* tr = strans + tag * KK;
    const float* d = sdelta + (t - 1) * 12;
    float s[9];
#pragma unroll
    for (int j = 0; j < 9; j++) s[j] = tr[j] + d[j];
    float m = s[0];
#pragma unroll
    for (int j = 1; j < 9; j++) m = fmaxf(m, s[j]);
    unsigned msk = 0;
#pragma unroll
    for (int j = 0; j < 9; j++) msk |= (s[j] == m) ? (1u << j) : 0u;
    return __ffs(msk) - 1;
}

// ---------------------------------------------------------------------------
// Fused kernel. blockIdx 0..63: scan block for batch b (wave-1 resident).
// blockIdx 64..575: producer block for (b, t-chunk), chunk-major order.
// ---------------------------------------------------------------------------
__global__ __launch_bounds__(THREADS, 1) void fused_kernel(
    const float* __restrict__ embeds,   // [B,T,H]
    const float* __restrict__ W,        // [K,H]
    const float* __restrict__ bias,     // [K]
    const float* __restrict__ trans,    // [K,K]
    float* __restrict__ out)            // [B + B*T]
{
    const int tid = threadIdx.x;
    const int wid = tid >> 5;
    const int lane = tid & 31;

    if (blockIdx.x >= NSCAN) {
        // ============================ PRODUCER ============================
        const int idx = blockIdx.x - NSCAN;
        const int c = idx >> 6;            // t-chunk 0..7 (low idx = low t)
        const int b = idx & 63;

        float* sWt = (float*)dsm;          // [h*11 + k], 33792 B
        for (int i = tid; i < KK * HH; i += THREADS) {
            int k = i / HH, h = i - k * HH;
            sWt[h * KK + k] = W[i];
        }
        __syncthreads();

        const int tb = c * 64 + wid * 4;   // this warp's 4 t-rows
        const float* A0 = embeds + ((size_t)b * TT + tb) * HH;

        float acc[4][KK];
#pragma unroll
        for (int r = 0; r < 4; r++)
#pragma unroll
            for (int k = 0; k < KK; k++) acc[r][k] = 0.0f;

#pragma unroll
        for (int w = 0; w < 6; w++) {
            float a[4][4];
#pragma unroll
            for (int r = 0; r < 4; r++)
#pragma unroll
                for (int s = 0; s < 4; s++)
                    a[r][s] = A0[(size_t)r * HH + w * 128 + s * 32 + lane];
#pragma unroll
            for (int s = 0; s < 4; s++) {
                float wr[KK];
                const float* wp = &sWt[(w * 128 + s * 32 + lane) * KK];
#pragma unroll
                for (int k = 0; k < KK; k++) wr[k] = wp[k];
#pragma unroll
                for (int r = 0; r < 4; r++)
#pragma unroll
                    for (int k = 0; k < KK; k++)
                        acc[r][k] = fmaf(a[r][s], wr[k], acc[r][k]);
            }
        }

#pragma unroll
        for (int r = 0; r < 4; r++)
#pragma unroll
            for (int k = 0; k < KK; k++) {
                float v = acc[r][k];
                v += __shfl_xor_sync(0xffffffffu, v, 16);
                v += __shfl_xor_sync(0xffffffffu, v, 8);
                v += __shfl_xor_sync(0xffffffffu, v, 4);
                v += __shfl_xor_sync(0xffffffffu, v, 2);
                v += __shfl_xor_sync(0xffffffffu, v, 1);
                acc[r][k] = v;
            }

        if (lane < KK) {
            const float bk = __ldg(&bias[lane]);
#pragma unroll
            for (int r = 0; r < 4; r++)
                g_feats[((size_t)b * TT + tb + r) * KK + lane] = acc[r][lane] + bk;
        }
        __syncthreads();
        if (tid == 0) {
            __threadfence();
            atomicExch(&g_cflag[b * 8 + c], 1);
        }
        return;
    }

    // ============================== SCAN BLOCK ==============================
    const int b = blockIdx.x;
    float* sdelta = (float*)dsm;                         // [t*12+slot] 24576 B
    float* strans = (float*)(dsm + 24576);               // 496 B
    unsigned char (*pseg)[32] = (unsigned char (*)[32])(dsm + 25072);  // 5632 B
    unsigned char* esel = (unsigned char*)(dsm + 30704); // 16 B
    int* s_lt = (int*)(dsm + 30720);

    for (int i = tid; i < KK * KK; i += THREADS) strans[i] = trans[i];
    __syncthreads();

    if (wid == 0) {
        const int target = (lane <= 8) ? lane : END_ID;
        const int slot4 = ((lane <= 8) ? lane : 9) * 4;

        float tr0 = strans[target * KK + 0], tr1 = strans[target * KK + 1];
        float tr2 = strans[target * KK + 2], tr3 = strans[target * KK + 3];
        float tr4 = strans[target * KK + 4], tr5 = strans[target * KK + 5];
        float tr6 = strans[target * KK + 6], tr7 = strans[target * KK + 7];
        float tr8 = strans[target * KK + 8], tr9 = strans[target * KK + 9];

        const float* fb = g_feats + (size_t)b * TT * KK;
        volatile int* fl = g_cflag + b * 8;

        // wait for chunk 0 (t=0..63)
        while (!fl[0]) {}
        __threadfence();

        const unsigned sd_base = (unsigned)__cvta_generic_to_shared(sdelta);
        float d0, d1, d2, d3, d4, d5, d6, d7, d8;

        // ---- t = 1 closed form: predecessor is START (certain) ----
        {
            float nd1 = (tr9 + 0.0f) + __ldg(&fb[KK + target]);
            unsigned row1 = sd_base + 48;
            asm volatile("st.shared.f32 [%0], %1;"
                         :: "r"(row1 + slot4), "f"(nd1) : "memory");
            asm volatile("ld.shared.v4.f32 {%0,%1,%2,%3}, [%4];"
                         : "=f"(d0), "=f"(d1), "=f"(d2), "=f"(d3)
                         : "r"(row1) : "memory");
            asm volatile("ld.shared.v4.f32 {%0,%1,%2,%3}, [%4+16];"
                         : "=f"(d4), "=f"(d5), "=f"(d6), "=f"(d7)
                         : "r"(row1) : "memory");
            asm volatile("ld.shared.f32 %0, [%1+32];"
                         : "=f"(d8) : "r"(row1) : "memory");
        }

        float fbuf[6];
#pragma unroll
        for (int s = 0; s < 6; s++) fbuf[s] = __ldg(&fb[(2 + s) * KK + target]);
        const float* fpre = fb + 8 * KK + target;

        unsigned addr = sd_base + 96;              // row 2
        unsigned sd_store = addr + slot4;

        int ahead = 0, pollc = 1;
        int fpoll = fl[1];                         // pipelined poll (next iter)

#define VSTEP(U_, O0, O1)                                                      \
        {                                                                      \
            float f = fbuf[U_];                                                \
            fbuf[U_] = __ldg(fpre); fpre += KK;                                \
            float s0 = tr0 + d0, s1 = tr1 + d1, s2 = tr2 + d2, s3 = tr3 + d3;  \
            float s4 = tr4 + d4, s5 = tr5 + d5, s6 = tr6 + d6, s7 = tr7 + d7;  \
            float s8v = tr8 + d8;                                              \
            float m01 = fmaxf(s0, s1), m23 = fmaxf(s2, s3);                    \
            float m45 = fmaxf(s4, s5), m67 = fmaxf(s6, s7);                    \
            float m = fmaxf(fmaxf(fmaxf(m01, m23), fmaxf(m45, m67)), s8v);     \
            float nd = m + f;                                                  \
            asm volatile("st.shared.f32 [%0+" #O0 "], %1;"                     \
                         :: "r"(sd_store), "f"(nd) : "memory");                \
            asm volatile("ld.shared.v4.f32 {%0,%1,%2,%3}, [%4+" #O0 "];"       \
                         : "=f"(d0), "=f"(d1), "=f"(d2), "=f"(d3)              \
                         : "r"(addr) : "memory");                              \
            asm volatile("ld.shared.v4.f32 {%0,%1,%2,%3}, [%4+" #O1 "];"       \
                         : "=f"(d4), "=f"(d5), "=f"(d6), "=f"(d7)              \
                         : "r"(addr) : "memory");                              \
            asm volatile("ld.shared.f32 %0, [%1+" #O1 "+16];"                  \
                         : "=f"(d8) : "r"(addr) : "memory");                   \
        }

        int t0 = 2;
        for (int it = 0; it < 85; ++it) {          // 85*6 = 510 steps, t=2..511
            if (fpoll) { ahead = (pollc > ahead) ? pollc : ahead;
                         pollc = (pollc < 7) ? pollc + 1 : 7; }
            int need = (t0 + 11) >> 6; need = (need < 7) ? need : 7;
            while (ahead < need) {                 // rare: producers behind
                if (fl[ahead + 1]) ahead++;
            }
            fpoll = fl[pollc];                     // issue; consumed next iter
            VSTEP(0, 0, 16)
            VSTEP(1, 48, 64)
            VSTEP(2, 96, 112)
            VSTEP(3, 144, 160)
            VSTEP(4, 192, 208)
            VSTEP(5, 240, 256)
            addr += 288;
            sd_store += 288;
            t0 += 6;
        }
#undef VSTEP

        __syncwarp();
        float dEND = sdelta[511 * 12 + 9];

        {
            float m01 = fmaxf(d0, d1), m23 = fmaxf(d2, d3);
            float m45 = fmaxf(d4, d5), m67 = fmaxf(d6, d7);
            float m = fmaxf(fmaxf(fmaxf(m01, m23), fmaxf(m45, m67)),
                            fmaxf(d8, dEND));
            unsigned msk = (d0 == m ? 1u : 0u) | (d1 == m ? 2u : 0u) |
                           (d2 == m ? 4u : 0u) | (d3 == m ? 8u : 0u) |
                           (d4 == m ? 16u : 0u) | (d5 == m ? 32u : 0u) |
                           (d6 == m ? 64u : 0u) | (d7 == m ? 128u : 0u) |
                           (d8 == m ? 256u : 0u) |
                           (dEND == m ? (1u << END_ID) : 0u);
            if (lane == 0) {
                out[b] = m;                        // score
                *s_lt = __ffs(msk) - 1;
            }
        }
    }
    __syncthreads();

    // ---- chunked backtrack, psi recomputed from stored deltas ----
    if (tid < 165) {                       // chunks 0..14 x 11 entry tags
        const int c = tid / KK;
        const int e = tid - c * KK;
        const int tb = 32 * c;
        int tag = e;
        for (int t = tb + 32; t > tb; --t) {
            tag = psi_step(strans, sdelta, t, tag);
            pseg[c * KK + e][t - 1 - tb] = (unsigned char)tag;
        }
    } else if (tid == 165) {               // chunk 15 from known last tag
        int tag = *s_lt;
        pseg[15 * KK][31] = (unsigned char)tag;
        for (int t = TT - 1; t > 480; --t) {
            tag = psi_step(strans, sdelta, t, tag);
            pseg[15 * KK][t - 1 - 480] = (unsigned char)tag;
        }
    }
    __syncthreads();

    if (tid == 0) {
        esel[15] = 0;
        int btag = pseg[15 * KK][0];       // tag at position 480
        for (int c = 14; c >= 0; --c) {
            esel[c] = (unsigned char)btag;
            btag = pseg[c * KK + btag][0];
        }
    }
    __syncthreads();

    for (int p = tid; p < TT; p += THREADS) {
        int c = p >> 5;
        out[BB + (size_t)b * TT + p] = (float)pseg[c * KK + esel[c]][p & 31];
    }
}

// ---------------------------------------------------------------------------
extern "C" void kernel_launch(void* const* d_in, const int* in_sizes, int n_in,
                              void* d_out, int out_size)
{
    const float* embeds = (const float*)d_in[0];   // [B,T,H]
    const float* W_fc   = (const float*)d_in[1];   // [K,H]
    const float* b_fc   = (const float*)d_in[2];   // [K]
    const float* trans  = (const float*)d_in[3];   // [K,K]
    float* out = (float*)d_out;

    cudaFuncSetAttribute(fused_kernel,
                         cudaFuncAttributeMaxDynamicSharedMemorySize, SMEM_LAUNCH);
    zero_flags_kernel<<<1, BB * 8>>>();
    fused_kernel<<<GRID, THREADS, SMEM_LAUNCH>>>(embeds, W_fc, b_fc, trans, out);
}

// round 13
// speedup vs baseline: 1.7489x; 1.3921x over previous
#include <cuda_runtime.h>
#include <cstdint>

#define BB 64
#define TT 512
#define HH 768
#define KK 11
#define START_ID 9
#define END_ID 10
#define NEGV (-10000.0f)
#define NROWS (BB*TT)            // 32768

__device__ __align__(16) float g_feats[NROWS * KK];

// ---------------------------------------------------------------------------
// Kernel 1: feats[row][k] = dot(A[row,:], W[k,:]) + bias[k]   (DRAM roofline)
// ---------------------------------------------------------------------------
__global__ __launch_bounds__(256) void feats_kernel(
    const float* __restrict__ A,      // [NROWS, HH]
    const float* __restrict__ W,      // [KK, HH]
    const float* __restrict__ bias)   // [KK]
{
    __shared__ float sWt[HH * KK];    // [h*11 + k], 33792 B

    const int tid = threadIdx.x;
    for (int i = tid; i < HH * KK; i += 256) {
        int k = i / HH, h = i - k * HH;
        sWt[h * KK + k] = W[i];
    }
    __syncthreads();

    const int lane = tid & 31;
    const int warp = tid >> 5;
    const int rowBase = blockIdx.x * 32 + warp * 4;

    float acc[4][KK];
#pragma unroll
    for (int r = 0; r < 4; r++)
#pragma unroll
        for (int k = 0; k < KK; k++) acc[r][k] = 0.0f;

#pragma unroll
    for (int w = 0; w < 6; w++) {
        float a[4][4];
#pragma unroll
        for (int r = 0; r < 4; r++)
#pragma unroll
            for (int s = 0; s < 4; s++)
                a[r][s] = A[(size_t)(rowBase + r) * HH + w * 128 + s * 32 + lane];
#pragma unroll
        for (int s = 0; s < 4; s++) {
            float wr[KK];
            const int hb = (w * 128 + s * 32 + lane) * KK;
#pragma unroll
            for (int k = 0; k < KK; k++) wr[k] = sWt[hb + k];
#pragma unroll
            for (int r = 0; r < 4; r++)
#pragma unroll
                for (int k = 0; k < KK; k++)
                    acc[r][k] = fmaf(a[r][s], wr[k], acc[r][k]);
        }
    }

#pragma unroll
    for (int r = 0; r < 4; r++)
#pragma unroll
        for (int k = 0; k < KK; k++) {
            float v = acc[r][k];
            v += __shfl_xor_sync(0xffffffffu, v, 16);
            v += __shfl_xor_sync(0xffffffffu, v, 8);
            v += __shfl_xor_sync(0xffffffffu, v, 4);
            v += __shfl_xor_sync(0xffffffffu, v, 2);
            v += __shfl_xor_sync(0xffffffffu, v, 1);
            acc[r][k] = v;
        }

    if (lane == 0) {
#pragma unroll
        for (int r = 0; r < 4; r++)
#pragma unroll
            for (int k = 0; k < KK; k++)
                g_feats[(size_t)(rowBase + r) * KK + k] = acc[r][k] + __ldg(&bias[k]);
    }
}

// ---------------------------------------------------------------------------
// psi recompute: argmax_j (trans[tag][j] + delta[t-1][j]), first-max wins.
// Only j=0..8 can win for t>=2; at t=1 winner is START. Bit-exact.
// ---------------------------------------------------------------------------
__device__ __forceinline__ int psi_step(const float* __restrict__ strans,
                                        const float* __restrict__ sdelta,
                                        int t, int tag)
{
    if (t == 1) return START_ID;
    const float* tr = strans + tag * KK;
    const float* d = sdelta + (t - 1) * 12;
    float s[9];
#pragma unroll
    for (int j = 0; j < 9; j++) s[j] = tr[j] + d[j];
    float m = s[0];
#pragma unroll
    for (int j = 1; j < 9; j++) m = fmaxf(m, s[j]);
    unsigned msk = 0;
#pragma unroll
    for (int j = 0; j < 9; j++) msk |= (s[j] == m) ? (1u << j) : 0u;
    return __ffs(msk) - 1;
}

// ---------------------------------------------------------------------------
// Kernel 2: Viterbi. One block per batch, 192 threads (6 warps).
// Staging overlapped with scan: warp w stages sfeat rows [88w, 88w+88)
// (242 float4 each), bumps a done-counter; warp 0 (the scan warp) stages
// strans + its own slice, then scans, polling counters only at the 5 slice
// crossings. Scan: 9 live predecessors, targets 0..8 + END(slot 9); transport
// = STS + 2x LDS.128 + LDS.32 with immediate offsets, 10-step unroll.
// Backtrack recomputes psi from stored deltas (exact).
// ---------------------------------------------------------------------------
__global__ __launch_bounds__(192) void viterbi_kernel(
    const float* __restrict__ trans,   // [KK, KK]
    float* __restrict__ out)           // [BB + BB*TT]
{
    const int b = blockIdx.x;
    const int tid = threadIdx.x;
    const int wid = tid >> 5;
    const int lane = tid & 31;

    __shared__ __align__(16) float sfeat[(TT + 12) * KK];   // 23056 B, stride 11
    __shared__ __align__(16) float sdelta[TT * 12];         // 24576 B
    __shared__ float strans[KK * KK];
    __shared__ unsigned char s_pathseg[16][KK][32];         // 5632 B
    __shared__ unsigned char s_esel[16];
    __shared__ int s_lasttag;
    __shared__ float s_score;
    __shared__ int s_cnt[6];

    if (tid < 6) s_cnt[tid] = 0;
    __syncthreads();                                 // flags zeroed before sets

    const float4* fsrc = (const float4*)(g_feats + (size_t)b * TT * KK);
    float4* fdst = (float4*)sfeat;

    if (wid != 0) {
        // stager warps 1..5: slice [242w, 242w+242) float4 (= rows 88w..88w+87)
        const int lo = 242 * wid;
        const int hi = (lo + 242 < 1408) ? lo + 242 : 1408;
        for (int i = lo + lane; i < hi; i += 32) fdst[i] = fsrc[i];
        __threadfence_block();
        atomicAdd(&s_cnt[wid], 1);                   // per-lane arrival
    } else {
        // ====================== SCAN WARP (warp 0) ======================
        for (int i = lane; i < KK * KK; i += 32) strans[i] = trans[i];
        for (int i = lane; i < 242; i += 32) fdst[i] = fsrc[i];   // rows 0..87
        __syncwarp();
        __threadfence_block();

        const int target = (lane <= 8) ? lane : END_ID;
        const int slot4 = ((lane <= 8) ? lane : 9) * 4;

        float tr0 = strans[target * KK + 0], tr1 = strans[target * KK + 1];
        float tr2 = strans[target * KK + 2], tr3 = strans[target * KK + 3];
        float tr4 = strans[target * KK + 4], tr5 = strans[target * KK + 5];
        float tr6 = strans[target * KK + 6], tr7 = strans[target * KK + 7];
        float tr8 = strans[target * KK + 8], tr9 = strans[target * KK + 9];

        const unsigned sd_base = (unsigned)__cvta_generic_to_shared(sdelta);
        float d0, d1, d2, d3, d4, d5, d6, d7, d8;

        // ---- t = 1 closed form: predecessor is START (certain) ----
        {
            float nd1 = (tr9 + 0.0f) + sfeat[KK + target];
            unsigned row1 = sd_base + 48;
            asm volatile("st.shared.f32 [%0], %1;"
                         :: "r"(row1 + slot4), "f"(nd1) : "memory");
            asm volatile("ld.shared.v4.f32 {%0,%1,%2,%3}, [%4];"
                         : "=f"(d0), "=f"(d1), "=f"(d2), "=f"(d3)
                         : "r"(row1) : "memory");
            asm volatile("ld.shared.v4.f32 {%0,%1,%2,%3}, [%4+16];"
                         : "=f"(d4), "=f"(d5), "=f"(d6), "=f"(d7)
                         : "r"(row1) : "memory");
            asm volatile("ld.shared.f32 %0, [%1+32];"
                         : "=f"(d8) : "r"(row1) : "memory");
        }

        float fbuf[10];
#pragma unroll
        for (int s = 0; s < 10; s++) fbuf[s] = sfeat[(2 + s) * KK + target];
        const float* fpre = sfeat + 12 * KK + target;

        unsigned addr = sd_base + 96;              // row 2
        unsigned sd_store = addr + slot4;

#define VSTEP(U_, O0, O1)                                                      \
        {                                                                      \
            float f = fbuf[U_];                                                \
            fbuf[U_] = *fpre; fpre += KK;                                      \
            float s0 = tr0 + d0, s1 = tr1 + d1, s2 = tr2 + d2, s3 = tr3 + d3;  \
            float s4 = tr4 + d4, s5 = tr5 + d5, s6 = tr6 + d6, s7 = tr7 + d7;  \
            float s8v = tr8 + d8;                                              \
            float m01 = fmaxf(s0, s1), m23 = fmaxf(s2, s3);                    \
            float m45 = fmaxf(s4, s5), m67 = fmaxf(s6, s7);                    \
            float m = fmaxf(fmaxf(fmaxf(m01, m23), fmaxf(m45, m67)), s8v);     \
            float nd = m + f;                                                  \
            asm volatile("st.shared.f32 [%0+" #O0 "], %1;"                     \
                         :: "r"(sd_store), "f"(nd) : "memory");                \
            asm volatile("ld.shared.v4.f32 {%0,%1,%2,%3}, [%4+" #O0 "];"       \
                         : "=f"(d0), "=f"(d1), "=f"(d2), "=f"(d3)              \
                         : "r"(addr) : "memory");                              \
            asm volatile("ld.shared.v4.f32 {%0,%1,%2,%3}, [%4+" #O1 "];"       \
                         : "=f"(d4), "=f"(d5), "=f"(d6), "=f"(d7)              \
                         : "r"(addr) : "memory");                              \
            asm volatile("ld.shared.f32 %0, [%1+" #O1 "+16];"                  \
                         : "=f"(d8) : "r"(addr) : "memory");                   \
        }

        // iteration it covers t = 2+10it .. 11+10it; prefetch touches t+10.
        // slice crossings (rows 88w first touched at it = 7,16,25,34,42).
        const int seg_s[6] = {0, 7, 16, 25, 34, 42};
        const int seg_e[6] = {7, 16, 25, 34, 42, 51};
        for (int seg = 0; seg < 6; ++seg) {
            if (seg) {
                while (*(volatile int*)&s_cnt[seg] != 32) {}
                __threadfence_block();
            }
            for (int it = seg_s[seg]; it < seg_e[seg]; ++it) {
                VSTEP(0, 0, 16)
                VSTEP(1, 48, 64)
                VSTEP(2, 96, 112)
                VSTEP(3, 144, 160)
                VSTEP(4, 192, 208)
                VSTEP(5, 240, 256)
                VSTEP(6, 288, 304)
                VSTEP(7, 336, 352)
                VSTEP(8, 384, 400)
                VSTEP(9, 432, 448)
                addr += 480;
                sd_store += 480;
            }
        }
#undef VSTEP

        __syncwarp();
        float dEND = sdelta[511 * 12 + 9];

        {
            float m01 = fmaxf(d0, d1), m23 = fmaxf(d2, d3);
            float m45 = fmaxf(d4, d5), m67 = fmaxf(d6, d7);
            float m = fmaxf(fmaxf(fmaxf(m01, m23), fmaxf(m45, m67)),
                            fmaxf(d8, dEND));
            unsigned msk = (d0 == m ? 1u : 0u) | (d1 == m ? 2u : 0u) |
                           (d2 == m ? 4u : 0u) | (d3 == m ? 8u : 0u) |
                           (d4 == m ? 16u : 0u) | (d5 == m ? 32u : 0u) |
                           (d6 == m ? 64u : 0u) | (d7 == m ? 128u : 0u) |
                           (d8 == m ? 256u : 0u) |
                           (dEND == m ? (1u << END_ID) : 0u);
            if (lane == 0) {
                s_score = m;
                s_lasttag = __ffs(msk) - 1;
            }
        }
    }
    __syncthreads();

    // ---- chunked backtrack, psi recomputed from stored deltas ----
    if (tid < 165) {                       // chunks 0..14 x 11 entry tags
        const int c = tid / KK;
        const int e = tid - c * KK;
        const int tb = 32 * c;
        int tag = e;
        for (int t = tb + 32; t > tb; --t) {
            tag = psi_step(strans, sdelta, t, tag);
            s_pathseg[c][e][t - 1 - tb] = (unsigned char)tag;
        }
    } else if (tid == 165) {               // chunk 15 from known last tag
        int tag = s_lasttag;
        s_pathseg[15][0][31] = (unsigned char)tag;
        for (int t = TT - 1; t > 480; --t) {
            tag = psi_step(strans, sdelta, t, tag);
            s_pathseg[15][0][t - 1 - 480] = (unsigned char)tag;
        }
    }
    __syncthreads();

    if (tid == 0) {
        s_esel[15] = 0;
        int btag = s_pathseg[15][0][0];    // tag at position 480
        for (int c = 14; c >= 0; --c) {
            s_esel[c] = (unsigned char)btag;
            btag = s_pathseg[c][btag][0];  // tag at position 32c
        }
    }
    __syncthreads();

    if (tid == 0) out[b] = s_score;
    for (int p = tid; p < TT; p += 192) {
        int c = p >> 5;
        out[BB + (size_t)b * TT + p] = (float)s_pathseg[c][s_esel[c]][p & 31];
    }
}

// ---------------------------------------------------------------------------
extern "C" void kernel_launch(void* const* d_in, const int* in_sizes, int n_in,
                              void* d_out, int out_size)
{
    const float* embeds = (const float*)d_in[0];   // [B,T,H]
    const float* W_fc   = (const float*)d_in[1];   // [K,H]
    const float* b_fc   = (const float*)d_in[2];   // [K]
    const float* trans  = (const float*)d_in[3];   // [K,K]
    float* out = (float*)d_out;

    feats_kernel<<<1024, 256>>>(embeds, W_fc, b_fc);
    viterbi_kernel<<<BB, 192>>>(trans, out);
}